// round 1
// baseline (speedup 1.0000x reference)
#include <cuda_runtime.h>
#include <cstdint>

// BorderLoss: mean( w * BCEwithlogits(x, y) ), w = 1 + border(y), border = 3x3dilate - 3x3erode.
// x: [64,512,512] f32, y: [64,512,512] i32 in {0,1}. Output: 1 float.
//
// Key identities:
//   loss = softplus((1-2y)*x)            (exact rewrite of max(x,0)-x*y+log1p(e^-|x|))
//   erode = AND over 3x3, dilate = OR over 3x3 (y binary), border = OR9 & ~AND9
//   w=2 applied as +1 to the float exponent (loss >= softplus(-6) ~ 2.5e-3, always normal)
//   SAME padding == index clamping (idempotent duplicates under min/max)

static constexpr int W  = 512;
static constexpr int H  = 512;
static constexpr int NI = 64;
static constexpr int ROWS_PER_WARP = 8;   // block = 4 warps -> 32 rows/block
static constexpr int STRIPS = H / (ROWS_PER_WARP * 4);  // 16

__global__ void bl_zero_out(float* o) {
    if (threadIdx.x == 0) *o = 0.0f;
}

__global__ __launch_bounds__(128)
void border_loss_kernel(const float* __restrict__ x,
                        const int*   __restrict__ y,
                        float* __restrict__ out)
{
    const int img   = blockIdx.x >> 4;     // 16 strips per image
    const int strip = blockIdx.x & 15;
    const int warp  = threadIdx.x >> 5;
    const int lane  = threadIdx.x & 31;
    const int row0  = strip * 32 + warp * ROWS_PER_WARP;
    const int col0  = lane * 16;           // 16 px per lane, 32 lanes = 512 cols

    const size_t imgoff = (size_t)img * H * W;
    const float* xbase = x + imgoff + (size_t)row0 * W + col0;
    const int*   ybase = y + imgoff + col0;

    // Packed mask rows: 4 regs x 4 bytes, byte value in {0, 0x80}
    unsigned pm[4], cm[4], nm[4];

    auto loadm = [&](int g, unsigned m[4]) {
        const int4* p = (const int4*)(ybase + (size_t)g * W);
#pragma unroll
        for (int j = 0; j < 4; j++) {
            int4 v = p[j];
            unsigned p01 = __byte_perm((unsigned)v.x, (unsigned)v.y, 0x0040);
            unsigned p23 = __byte_perm((unsigned)v.z, (unsigned)v.w, 0x0040);
            m[j] = __byte_perm(p01, p23, 0x5410) << 7;   // each byte: y<<7
        }
    };

    loadm(row0 == 0 ? 0 : row0 - 1, pm);   // row clamp (idempotent for min/max)
    loadm(row0, cm);

    float acc = 0.0f;

#pragma unroll
    for (int r = 0; r < ROWS_PER_WARP; r++) {
        const int g = row0 + r;
        if (g + 1 < H) {
            loadm(g + 1, nm);
        } else {
#pragma unroll
            for (int j = 0; j < 4; j++) nm[j] = cm[j];   // bottom clamp
        }

        // Vertical 3-tap: AND = min, OR = max (bytes in {0,0x80})
        unsigned vmn[4], vmx[4];
#pragma unroll
        for (int j = 0; j < 4; j++) {
            vmn[j] = pm[j] & cm[j] & nm[j];
            vmx[j] = pm[j] | cm[j] | nm[j];
        }

        // Cross-lane halo: pack (min,max) edge bytes, one shfl each direction.
        unsigned el = __byte_perm(vmn[0], vmx[0], 0x0040); // b0=vmn[0].b0, b1=vmx[0].b0
        unsigned eh = __byte_perm(vmn[3], vmx[3], 0x0073); // b0=vmn[3].b3, b1=vmx[3].b3
        unsigned fromL = __shfl_up_sync(0xffffffffu, eh, 1);
        unsigned fromR = __shfl_down_sync(0xffffffffu, el, 1);
        if (lane == 0)  fromL = el;   // col clamp: duplicate own col 0
        if (lane == 31) fromR = eh;   // col clamp: duplicate own col 511

        unsigned border[4];
#pragma unroll
        for (int j = 0; j < 4; j++) {
            unsigned Lmn = (j == 0) ? __byte_perm(vmn[0], fromL, 0x2104)
                                    : __byte_perm(vmn[j], vmn[j-1], 0x2107);
            unsigned Lmx = (j == 0) ? __byte_perm(vmx[0], fromL, 0x2105)
                                    : __byte_perm(vmx[j], vmx[j-1], 0x2107);
            unsigned Rmn = (j == 3) ? __byte_perm(vmn[3], fromR, 0x4321)
                                    : __byte_perm(vmn[j], vmn[j+1], 0x4321);
            unsigned Rmx = (j == 3) ? __byte_perm(vmx[3], fromR, 0x5321)
                                    : __byte_perm(vmx[j], vmx[j+1], 0x4321);
            // border byte = dilate & ~erode  in {0, 0x80}
            border[j] = (vmx[j] | Lmx | Rmx) & ~(vmn[j] & Lmn & Rmn);
        }

        // Loss + weight + accumulate
        const float4* xr = (const float4*)(xbase + (size_t)r * W);
#pragma unroll
        for (int j = 0; j < 4; j++) {
            float4 xv = xr[j];
            float xs0 = xv.x, xs1 = xv.y, xs2 = xv.z, xs3 = xv.w;
            float xsv[4] = {xs0, xs1, xs2, xs3};
#pragma unroll
            for (int i = 0; i < 4; i++) {
                // sign mask: 0x80000000 iff y==1 (cm byte i is 0x80)
                unsigned sgn = __byte_perm(cm[j], 0u, 0x0444 | (i << 12));
                float z = __int_as_float(__float_as_int(xsv[i]) ^ sgn);
                // softplus(z), z in [-6,6]: no overflow possible
                float u = __expf(z);
                float l = __logf(1.0f + u);
                // weight: +0x00800000 to exponent iff border (exact *2)
                unsigned wb = __byte_perm(border[j], 0u, 0x4044 | (i << 8));
                acc += __int_as_float(__float_as_int(l) + wb);
            }
        }

        // rotate rows
#pragma unroll
        for (int j = 0; j < 4; j++) { pm[j] = cm[j]; cm[j] = nm[j]; }
    }

    // Reduce: warp shfl, then 4 partials through smem, one atomic per block.
#pragma unroll
    for (int o = 16; o; o >>= 1)
        acc += __shfl_down_sync(0xffffffffu, acc, o);

    __shared__ float ws[4];
    if (lane == 0) ws[warp] = acc;
    __syncthreads();
    if (threadIdx.x == 0) {
        float s = (ws[0] + ws[1]) + (ws[2] + ws[3]);
        atomicAdd(out, s * (1.0f / (float)(NI * H * W)));
    }
}

extern "C" void kernel_launch(void* const* d_in, const int* in_sizes, int n_in,
                              void* d_out, int out_size)
{
    const float* x = (const float*)d_in[0];
    const int*   y = (const int*)d_in[1];
    float* out = (float*)d_out;

    bl_zero_out<<<1, 32>>>(out);
    border_loss_kernel<<<NI * STRIPS, 128>>>(x, y, out);
}